// round 2
// baseline (speedup 1.0000x reference)
#include <cuda_runtime.h>

// ---------------- problem constants ----------------
#define NB   32        // batch
#define CIN  256
#define COUT 512
#define HW   16        // 4x4 spatial
#define KTOT 65536     // CIN*CIN
#define S2   256       // K-splits in main GEMM
#define KC3  32        // K-chunk staged per iteration
#define CH3  8         // KTOT / (S2*KC3)

typedef unsigned long long ull;

// packed f32x2 FMA: acc(lo,hi) += a(lo,hi)*b(lo,hi)  (exact fp32, 2 FMA/instr)
#define FMA2(acc, a, b) \
    asm("fma.rn.f32x2 %0, %1, %2, %0;" : "+l"(acc) : "l"(a), "l"(b))

__device__ __forceinline__ float unpack_sum(ull v) {
    float lo, hi;
    asm("mov.b64 {%0, %1}, %2;" : "=f"(lo), "=f"(hi) : "l"(v));
    return lo + hi;
}

// ---------------- scratch (__device__ globals; no allocs allowed) ----------
__device__ float g_y[NB * CIN * HW];              // y[b][c'][hw]          512 KB
__device__ float g_xsum[NB * CIN];                // X[b][c]                32 KB
__device__ float g_G[NB * KTOT];                  // G[b][c*256+c']          8 MB
__device__ float g_part[(S2 + 1) * NB * COUT];    // partials [s][b][o]   16.8 MB (slot S2 = bias)

// ============================================================
// K1: y = relu(W1 x + b1), and Xsum = sum_hw x
// grid (4, 32) = (cgroup, b), 256 threads
// ============================================================
__global__ void __launch_bounds__(256) k1_y(const float* __restrict__ x,
                                            const float* __restrict__ W1,
                                            const float* __restrict__ b1)
{
    __shared__ float xs[CIN * HW];   // 16 KB
    const int b  = blockIdx.y;
    const int cg = blockIdx.x;
    const int t  = threadIdx.x;

    {
        const float4* xv  = (const float4*)(x + (size_t)b * CIN * HW);
        float4*       xsv = (float4*)xs;
        for (int i = t; i < CIN * HW / 4; i += 256) xsv[i] = xv[i];
    }
    __syncthreads();

    const int cp  = cg * 64 + (t >> 2);   // output channel c'
    const int hw0 = (t & 3) * 4;          // this thread's 4 hw positions

    float bv = b1[cp];
    float a0 = bv, a1 = bv, a2 = bv, a3 = bv;

    const float4* w1v = (const float4*)(W1 + (size_t)cp * CIN);
    #pragma unroll 4
    for (int c4 = 0; c4 < CIN / 4; c4++) {
        float4 w = w1v[c4];
        const float* xp = xs + c4 * 4 * HW + hw0;
        a0 += w.x * xp[0];      a1 += w.x * xp[1];      a2 += w.x * xp[2];      a3 += w.x * xp[3];
        a0 += w.y * xp[16];     a1 += w.y * xp[17];     a2 += w.y * xp[18];     a3 += w.y * xp[19];
        a0 += w.z * xp[32];     a1 += w.z * xp[33];     a2 += w.z * xp[34];     a3 += w.z * xp[35];
        a0 += w.w * xp[48];     a1 += w.w * xp[49];     a2 += w.w * xp[50];     a3 += w.w * xp[51];
    }

    float4 r;
    r.x = fmaxf(a0, 0.f); r.y = fmaxf(a1, 0.f); r.z = fmaxf(a2, 0.f); r.w = fmaxf(a3, 0.f);
    *(float4*)(g_y + ((size_t)b * CIN + cp) * HW + hw0) = r;

    if (cg == 0) {   // Xsum[b][c], c = t
        float s = 0.f;
        #pragma unroll
        for (int h = 0; h < HW; h++) s += xs[t * HW + h];
        g_xsum[b * CIN + t] = s;
    }
}

// ============================================================
// K2: G[b][c*256+c'] = sum_hw x[b,c,hw]*y[b,c',hw]
// grid (8, 32) = (cgroup of 32 c-rows, b), 256 threads (thread = c')
// ============================================================
__global__ void __launch_bounds__(256) k2_G(const float* __restrict__ x)
{
    __shared__ float xs2[32 * HW];
    const int b  = blockIdx.y;
    const int cg = blockIdx.x;
    const int t  = threadIdx.x;

    {
        const float4* xv = (const float4*)(x + ((size_t)b * CIN + cg * 32) * HW);
        float4*       sv = (float4*)xs2;
        for (int i = t; i < 32 * HW / 4; i += 256) sv[i] = xv[i];
    }

    float yr[HW];
    {
        const float4* yv = (const float4*)(g_y + ((size_t)b * CIN + t) * HW);
        #pragma unroll
        for (int i = 0; i < 4; i++) {
            float4 v = yv[i];
            yr[i * 4 + 0] = v.x; yr[i * 4 + 1] = v.y; yr[i * 4 + 2] = v.z; yr[i * 4 + 3] = v.w;
        }
    }
    __syncthreads();

    float* Gb = g_G + (size_t)b * KTOT + cg * 32 * 256 + t;
    #pragma unroll 4
    for (int j = 0; j < 32; j++) {
        const float* xj = xs2 + j * HW;
        float v = 0.f;
        #pragma unroll
        for (int h = 0; h < HW; h++) v += xj[h] * yr[h];
        Gb[(size_t)j * 256] = v;
    }
}

// ============================================================
// K_bias: bias[b][o] = sum_c b2[o*256+c]*Xsum[b][c] -> g_part slot S2
// grid 64 blocks (8 o rows each), 256 threads = 32 b x 8 o
// ============================================================
__global__ void __launch_bounds__(256) k_bias(const float* __restrict__ b2)
{
    __shared__ float xsT[CIN][33];   // transposed Xsum, padded (33.8 KB)
    __shared__ float b2s[8][CIN];    // 8 b2 rows (8 KB)
    const int tid = threadIdx.x;
    const int o0  = blockIdx.x * 8;

    for (int i = tid; i < NB * CIN; i += 256) {
        int b = i >> 8, c = i & 255;
        xsT[c][b] = g_xsum[i];
    }
    for (int i = tid; i < 8 * CIN; i += 256) {
        b2s[i >> 8][i & 255] = b2[(size_t)o0 * CIN + i];
    }
    __syncthreads();

    const int b  = tid & 31;
    const int ol = tid >> 5;
    float acc = 0.f;
    #pragma unroll 8
    for (int c = 0; c < CIN; c++) acc += b2s[ol][c] * xsT[c][b];

    g_part[((size_t)S2 * NB + b) * COUT + o0 + ol] = acc;
}

// ============================================================
// K3: main GEMM partials via packed f32x2 FFMA
//   part[s][b][o] = sum_{k in slice} G[b][k] * W2[o*KTOT + k]
// grid (4, S2) = (o-tile of 128, k-split), 256 threads
// thread tile: 4 b x 4 o  (warp w -> b = 4w..4w+3; lane -> o = o0..o0+3)
// ============================================================
__global__ void __launch_bounds__(256) k3_gemm(const float* __restrict__ W2)
{
    __shared__ float sG[32][KC3 + 4];   // row stride 36 floats (144B, 8B-aligned)

    const int og   = blockIdx.x;
    const int s    = blockIdx.y;
    const int tid  = threadIdx.x;
    const int lane = tid & 31;
    const int w    = tid >> 5;
    const int o0   = og * 128 + lane * 4;
    const int b0   = w * 4;

    ull acc[4][4];
    #pragma unroll
    for (int i = 0; i < 4; i++)
        #pragma unroll
        for (int j = 0; j < 4; j++) acc[i][j] = 0ull;   // packed (+0,+0)

    const ulonglong2* w2p0 = (const ulonglong2*)(W2 + (size_t)(o0 + 0) * KTOT);
    const ulonglong2* w2p1 = (const ulonglong2*)(W2 + (size_t)(o0 + 1) * KTOT);
    const ulonglong2* w2p2 = (const ulonglong2*)(W2 + (size_t)(o0 + 2) * KTOT);
    const ulonglong2* w2p3 = (const ulonglong2*)(W2 + (size_t)(o0 + 3) * KTOT);

    const int kbase = s * (CH3 * KC3);
    const int bb  = tid >> 3;     // staging: b row
    const int kk4 = tid & 7;      // staging: float4 slot

    for (int ch = 0; ch < CH3; ch++) {
        const int k0 = kbase + ch * KC3;

        __syncthreads();
        *((float4*)&sG[bb][kk4 * 4]) =
            *(const float4*)(g_G + (size_t)bb * KTOT + k0 + kk4 * 4);
        __syncthreads();

        const int kq0 = k0 >> 2;   // double2 index into W2 rows
        #pragma unroll
        for (int kk = 0; kk < KC3 / 4; kk++) {
            ulonglong2 w0 = w2p0[kq0 + kk];
            ulonglong2 w1 = w2p1[kq0 + kk];
            ulonglong2 w2v = w2p2[kq0 + kk];
            ulonglong2 w3 = w2p3[kq0 + kk];
            #pragma unroll
            for (int i = 0; i < 4; i++) {
                const ull* gp = (const ull*)&sG[b0 + i][0];
                ull g01 = gp[kk * 2 + 0];   // (k, k+1) packed — broadcast LDS.64
                ull g23 = gp[kk * 2 + 1];   // (k+2, k+3)
                FMA2(acc[i][0], g01, w0.x);  FMA2(acc[i][0], g23, w0.y);
                FMA2(acc[i][1], g01, w1.x);  FMA2(acc[i][1], g23, w1.y);
                FMA2(acc[i][2], g01, w2v.x); FMA2(acc[i][2], g23, w2v.y);
                FMA2(acc[i][3], g01, w3.x);  FMA2(acc[i][3], g23, w3.y);
            }
        }
    }

    #pragma unroll
    for (int i = 0; i < 4; i++) {
        float4 v;
        v.x = unpack_sum(acc[i][0]);
        v.y = unpack_sum(acc[i][1]);
        v.z = unpack_sum(acc[i][2]);
        v.w = unpack_sum(acc[i][3]);
        *(float4*)(g_part + ((size_t)s * NB + b0 + i) * COUT + o0) = v;
    }
}

// ============================================================
// K4: out[b][o] = sum over S2+1 partial slots (slot S2 carries bias)
// grid 256 blocks x 256 threads: 64 outputs/block x 4 reducers
// ============================================================
__global__ void __launch_bounds__(256) k4_reduce(float* __restrict__ out)
{
    __shared__ float red[256];
    const int tid = threadIdx.x;
    const int r   = tid >> 6;            // reducer id 0..3
    const int ml  = tid & 63;
    const int m   = blockIdx.x * 64 + ml;

    const int s0 = r * 64;
    const int s1 = (r == 3) ? (S2 + 1) : (s0 + 64);

    float s = 0.f;
    #pragma unroll 8
    for (int sp = s0; sp < s1; sp++)
        s += g_part[(size_t)sp * (NB * COUT) + m];   // coalesced

    red[tid] = s;
    __syncthreads();
    if (tid < 64) {
        out[blockIdx.x * 64 + tid] =
            red[tid] + red[tid + 64] + red[tid + 128] + red[tid + 192];
    }
}

// ============================================================
extern "C" void kernel_launch(void* const* d_in, const int* in_sizes, int n_in,
                              void* d_out, int out_size)
{
    const float* x  = (const float*)d_in[0];
    const float* W1 = (const float*)d_in[1];
    const float* b1 = (const float*)d_in[2];
    const float* W2 = (const float*)d_in[3];
    const float* b2 = (const float*)d_in[4];
    // d_in[5] (Wa), d_in[6] (ba): attention branch is dead code in the reference.
    float* out = (float*)d_out;

    k1_y   <<<dim3(4, NB), 256>>>(x, W1, b1);
    k2_G   <<<dim3(8, NB), 256>>>(x);
    k_bias <<<64, 256>>>(b2);
    k3_gemm<<<dim3(4, S2), 256>>>(W2);
    k4_reduce<<<(NB * COUT) / 64, 256>>>(out);
}

// round 3
// speedup vs baseline: 4.4042x; 4.4042x over previous
#include <cuda_runtime.h>

// ---------------- problem constants ----------------
#define NB   32        // batch
#define CIN  256
#define COUT 512
#define HW   16        // 4x4 spatial
#define KTOT 65536     // CIN*CIN
#define S3   128       // K-splits in main GEMM
#define KCH  32        // K per chunk
#define NCH  16        // chunks per split (KTOT / (S3*KCH))
#define OTILE 64       // o rows per block

typedef unsigned long long ull;

// packed f32x2 FMA: acc(lo,hi) += a(lo,hi)*b(lo,hi)  (exact fp32, 2 FMA/instr)
#define FMA2(acc, a, b) \
    asm("fma.rn.f32x2 %0, %1, %2, %0;" : "+l"(acc) : "l"(a), "l"(b))

// LDS.128 into two b64 regs (no pack movs)
#define LDS2(lo, hi, addr) \
    asm("ld.shared.v2.b64 {%0,%1}, [%2];" : "=l"(lo), "=l"(hi) : "r"(addr))

__device__ __forceinline__ float unpack_sum(ull v) {
    float lo, hi;
    asm("mov.b64 {%0, %1}, %2;" : "=f"(lo), "=f"(hi) : "l"(v));
    return lo + hi;
}

// ---------------- scratch ----------------
__device__ float g_y[NB * CIN * HW];              // y[b][c'][hw]          512 KB
__device__ float g_xsum[NB * CIN];                //                        32 KB
__device__ float g_G2[(KTOT / KCH) * NB * KCH];   // [kchunk][b][kin]        8 MB
__device__ float g_part[(S3 + 1) * NB * COUT];    // [s][b][o], slot S3=bias 8.5 MB

// ============================================================
// K1: y = relu(W1 x + b1), and Xsum = sum_hw x
// ============================================================
__global__ void __launch_bounds__(256) k1_y(const float* __restrict__ x,
                                            const float* __restrict__ W1,
                                            const float* __restrict__ b1)
{
    __shared__ float xs[CIN * HW];
    const int b  = blockIdx.y;
    const int cg = blockIdx.x;
    const int t  = threadIdx.x;

    {
        const float4* xv  = (const float4*)(x + (size_t)b * CIN * HW);
        float4*       xsv = (float4*)xs;
        for (int i = t; i < CIN * HW / 4; i += 256) xsv[i] = xv[i];
    }
    __syncthreads();

    const int cp  = cg * 64 + (t >> 2);
    const int hw0 = (t & 3) * 4;

    float bv = b1[cp];
    float a0 = bv, a1 = bv, a2 = bv, a3 = bv;

    const float4* w1v = (const float4*)(W1 + (size_t)cp * CIN);
    #pragma unroll 4
    for (int c4 = 0; c4 < CIN / 4; c4++) {
        float4 w = w1v[c4];
        const float* xp = xs + c4 * 4 * HW + hw0;
        a0 += w.x * xp[0];      a1 += w.x * xp[1];      a2 += w.x * xp[2];      a3 += w.x * xp[3];
        a0 += w.y * xp[16];     a1 += w.y * xp[17];     a2 += w.y * xp[18];     a3 += w.y * xp[19];
        a0 += w.z * xp[32];     a1 += w.z * xp[33];     a2 += w.z * xp[34];     a3 += w.z * xp[35];
        a0 += w.w * xp[48];     a1 += w.w * xp[49];     a2 += w.w * xp[50];     a3 += w.w * xp[51];
    }

    float4 r;
    r.x = fmaxf(a0, 0.f); r.y = fmaxf(a1, 0.f); r.z = fmaxf(a2, 0.f); r.w = fmaxf(a3, 0.f);
    *(float4*)(g_y + ((size_t)b * CIN + cp) * HW + hw0) = r;

    if (cg == 0) {
        float s = 0.f;
        #pragma unroll
        for (int h = 0; h < HW; h++) s += xs[t * HW + h];
        g_xsum[b * CIN + t] = s;
    }
}

// ============================================================
// K2: G[b][k] = sum_hw x[b,c,hw]*y[b,c',hw], k = c*256+c'
// writes chunk-blocked g_G2[k>>5][b][k&31]  (coalesced: lane = c' low bits)
// grid (8, 32), 256 threads (thread = c')
// ============================================================
__global__ void __launch_bounds__(256) k2_G(const float* __restrict__ x)
{
    __shared__ float xs2[32 * HW];
    const int b  = blockIdx.y;
    const int cg = blockIdx.x;
    const int t  = threadIdx.x;

    {
        const float4* xv = (const float4*)(x + ((size_t)b * CIN + cg * 32) * HW);
        float4*       sv = (float4*)xs2;
        for (int i = t; i < 32 * HW / 4; i += 256) sv[i] = xv[i];
    }

    float yr[HW];
    {
        const float4* yv = (const float4*)(g_y + ((size_t)b * CIN + t) * HW);
        #pragma unroll
        for (int i = 0; i < 4; i++) {
            float4 v = yv[i];
            yr[i * 4 + 0] = v.x; yr[i * 4 + 1] = v.y; yr[i * 4 + 2] = v.z; yr[i * 4 + 3] = v.w;
        }
    }
    __syncthreads();

    const int wk  = t >> 5;   // which 32-sub-chunk of c' this thread is in
    const int kin = t & 31;

    #pragma unroll 4
    for (int j = 0; j < 32; j++) {
        const float* xj = xs2 + j * HW;
        float v = 0.f;
        #pragma unroll
        for (int h = 0; h < HW; h++) v += xj[h] * yr[h];
        // k = (cg*32+j)*256 + t ; kchunk = (cg*32+j)*8 + wk ; addr coalesced over kin
        int kc = (cg * 32 + j) * 8 + wk;
        g_G2[(size_t)kc * (NB * KCH) + b * KCH + kin] = v;
    }
}

// ============================================================
// K_bias: bias[b][o] = sum_c b2[o*256+c]*Xsum[b][c] -> g_part slot S3
// ============================================================
__global__ void __launch_bounds__(256) k_bias(const float* __restrict__ b2)
{
    __shared__ float xsT[CIN][33];
    __shared__ float b2s[8][CIN];
    const int tid = threadIdx.x;
    const int o0  = blockIdx.x * 8;

    for (int i = tid; i < NB * CIN; i += 256) {
        int b = i >> 8, c = i & 255;
        xsT[c][b] = g_xsum[i];
    }
    for (int i = tid; i < 8 * CIN; i += 256) {
        b2s[i >> 8][i & 255] = b2[(size_t)o0 * CIN + i];
    }
    __syncthreads();

    const int b  = tid & 31;
    const int ol = tid >> 5;
    float acc = 0.f;
    #pragma unroll 8
    for (int c = 0; c < CIN; c++) acc += b2s[ol][c] * xsT[c][b];

    g_part[((size_t)S3 * NB + b) * COUT + o0 + ol] = acc;
}

// ============================================================
// K3: part[s][b][o] = sum_{k in slice} G[b][k] * W2[o*KTOT + k]
// grid (COUT/OTILE, S3) = (8, 128), 256 threads (8 warps)
// lane = b (32 batches); warp w owns o rows [w*8, w*8+8) of the 64-o tile
// acc packed over k-parity via fma.rn.f32x2
// ============================================================
__global__ void __launch_bounds__(256) k3_gemm(const float* __restrict__ W2)
{
    __shared__ float sW[2][OTILE][36];  // [buf][ro][kc], row 144B (16B-aligned)
    __shared__ float sG[2][NB][36];     // [buf][b][kin]

    const int og   = blockIdx.x;
    const int s    = blockIdx.y;
    const int tid  = threadIdx.x;
    const int lane = tid & 31;          // = b
    const int w    = tid >> 5;
    const int o0   = og * OTILE;
    const int kbase = s * (NCH * KCH);
    const int chb0  = kbase >> 5;       // global chunk index base into g_G2

    // staging thread mapping: i -> (ro, q): ro = i>>3 (row), q = i&7 (k-quad)
    const int ro1 = tid >> 3;           // 0..31
    const int q1  = tid & 7;
    const int gb  = tid >> 3;           // g staging: b row (0..31)

    ull acc[8];
    #pragma unroll
    for (int i = 0; i < 8; i++) acc[i] = 0ull;

    const unsigned sWb = (unsigned)__cvta_generic_to_shared(&sW[0][0][0]);
    const unsigned sGb = (unsigned)__cvta_generic_to_shared(&sG[0][0][0]);
    const unsigned sWstride = OTILE * 36 * 4;   // bytes per buffer
    const unsigned sGstride = NB * 36 * 4;

    // ---- prologue: stage chunk 0 ----
    float4 wa = *(const float4*)(W2 + (size_t)(o0 + ro1) * KTOT + kbase + 4 * q1);
    float4 wb = *(const float4*)(W2 + (size_t)(o0 + ro1 + 32) * KTOT + kbase + 4 * q1);
    float4 ga = *(const float4*)(g_G2 + (size_t)chb0 * (NB * KCH) + gb * KCH + 4 * q1);
    *(float4*)&sW[0][ro1][4 * q1]      = wa;
    *(float4*)&sW[0][ro1 + 32][4 * q1] = wb;
    *(float4*)&sG[0][gb][4 * q1]       = ga;
    __syncthreads();

    for (int ch = 0; ch < NCH; ch++) {
        const int cur = ch & 1;

        // prefetch next chunk from global (overlaps with compute below)
        if (ch + 1 < NCH) {
            const int k0n = kbase + (ch + 1) * KCH;
            wa = *(const float4*)(W2 + (size_t)(o0 + ro1) * KTOT + k0n + 4 * q1);
            wb = *(const float4*)(W2 + (size_t)(o0 + ro1 + 32) * KTOT + k0n + 4 * q1);
            ga = *(const float4*)(g_G2 + (size_t)(chb0 + ch + 1) * (NB * KCH) + gb * KCH + 4 * q1);
        }

        // G row for this lane's b into registers (16 ull = 32 k values)
        ull g[16];
        {
            unsigned ga0 = sGb + cur * sGstride + lane * 144;
            #pragma unroll
            for (int q = 0; q < 8; q++)
                LDS2(g[2 * q], g[2 * q + 1], ga0 + q * 16);
        }

        // compute: 8 o rows, uniform W2 broadcasts
        #pragma unroll
        for (int oo = 0; oo < 8; oo++) {
            unsigned wad = sWb + cur * sWstride + (w * 8 + oo) * 144;
            ull a = acc[oo];
            #pragma unroll
            for (int q = 0; q < 8; q++) {
                ull w0, w1;
                LDS2(w0, w1, wad + q * 16);
                FMA2(a, w0, g[2 * q]);
                FMA2(a, w1, g[2 * q + 1]);
            }
            acc[oo] = a;
        }

        __syncthreads();
        if (ch + 1 < NCH) {
            const int nxt = (ch + 1) & 1;
            *(float4*)&sW[nxt][ro1][4 * q1]      = wa;
            *(float4*)&sW[nxt][ro1 + 32][4 * q1] = wb;
            *(float4*)&sG[nxt][gb][4 * q1]       = ga;
            __syncthreads();
        }
    }

    // epilogue: 8 consecutive o per thread -> two float4 stores
    float r[8];
    #pragma unroll
    for (int oo = 0; oo < 8; oo++) r[oo] = unpack_sum(acc[oo]);
    float* dst = g_part + ((size_t)s * NB + lane) * COUT + o0 + w * 8;
    *(float4*)(dst + 0) = make_float4(r[0], r[1], r[2], r[3]);
    *(float4*)(dst + 4) = make_float4(r[4], r[5], r[6], r[7]);
}

// ============================================================
// K4: out[b][o] = sum over S3+1 partial slots
// grid 256 x 256: 64 outputs/block x 4 reducers
// ============================================================
__global__ void __launch_bounds__(256) k4_reduce(float* __restrict__ out)
{
    __shared__ float red[256];
    const int tid = threadIdx.x;
    const int r   = tid >> 6;
    const int ml  = tid & 63;
    const int m   = blockIdx.x * 64 + ml;

    const int s0 = r * 32;
    const int s1 = (r == 3) ? (S3 + 1) : (s0 + 32);

    float s = 0.f;
    #pragma unroll 8
    for (int sp = s0; sp < s1; sp++)
        s += g_part[(size_t)sp * (NB * COUT) + m];

    red[tid] = s;
    __syncthreads();
    if (tid < 64) {
        out[blockIdx.x * 64 + tid] =
            red[tid] + red[tid + 64] + red[tid + 128] + red[tid + 192];
    }
}

// ============================================================
extern "C" void kernel_launch(void* const* d_in, const int* in_sizes, int n_in,
                              void* d_out, int out_size)
{
    const float* x  = (const float*)d_in[0];
    const float* W1 = (const float*)d_in[1];
    const float* b1 = (const float*)d_in[2];
    const float* W2 = (const float*)d_in[3];
    const float* b2 = (const float*)d_in[4];
    // d_in[5] (Wa), d_in[6] (ba): attention branch is dead code in the reference.
    float* out = (float*)d_out;

    k1_y   <<<dim3(4, NB), 256>>>(x, W1, b1);
    k2_G   <<<dim3(8, NB), 256>>>(x);
    k_bias <<<64, 256>>>(b2);
    k3_gemm<<<dim3(COUT / OTILE, S3), 256>>>(W2);
    k4_reduce<<<(NB * COUT) / 64, 256>>>(out);
}

// round 4
// speedup vs baseline: 5.8815x; 1.3354x over previous
#include <cuda_runtime.h>
#include <cstdint>

// ---------------- problem constants ----------------
#define NB   32        // batch
#define CIN  256
#define COUT 512
#define HW   16        // 4x4 spatial
#define KTOT 65536     // CIN*CIN
#define S3   128       // K-splits in main GEMM
#define KCH  32        // K per chunk
#define NCH  16        // chunks per split (KTOT / (S3*KCH))
#define OTB  256       // o per block in k3

typedef unsigned long long ull;

// packed f32x2 FMA: acc(lo,hi) += a(lo,hi)*b(lo,hi)  (exact fp32, 2 FMA/instr)
#define FMA2(acc, a, b) \
    asm("fma.rn.f32x2 %0, %1, %2, %0;" : "+l"(acc) : "l"(a), "l"(b))

// LDS.128 into two b64 regs
#define LDS2(lo, hi, addr) \
    asm("ld.shared.v2.b64 {%0,%1}, [%2];" : "=l"(lo), "=l"(hi) : "r"(addr))

#define CP_ASYNC16(dst, src) \
    asm volatile("cp.async.cg.shared.global [%0], [%1], 16;" :: "r"(dst), "l"(src))
#define CP_COMMIT() asm volatile("cp.async.commit_group;")
#define CP_WAIT(n)  asm volatile("cp.async.wait_group %0;" :: "n"(n))

__device__ __forceinline__ float unpack_sum(ull v) {
    float lo, hi;
    asm("mov.b64 {%0, %1}, %2;" : "=f"(lo), "=f"(hi) : "l"(v));
    return lo + hi;
}

// ---------------- scratch ----------------
__device__ float g_y[NB * CIN * HW];              // y[b][c'][hw]          512 KB
__device__ float g_xsum[NB * CIN];                //                        32 KB
__device__ float g_G2[(KTOT / KCH) * NB * KCH];   // [kchunk][b][kin]        8 MB
__device__ float g_part[(S3 + 1) * NB * COUT];    // [s][b][o], slot S3=bias 8.5 MB

// ============================================================
// K1: y = relu(W1 x + b1), and Xsum = sum_hw x
// ============================================================
__global__ void __launch_bounds__(256) k1_y(const float* __restrict__ x,
                                            const float* __restrict__ W1,
                                            const float* __restrict__ b1)
{
    __shared__ float xs[CIN * HW];
    const int b  = blockIdx.y;
    const int cg = blockIdx.x;
    const int t  = threadIdx.x;

    {
        const float4* xv  = (const float4*)(x + (size_t)b * CIN * HW);
        float4*       xsv = (float4*)xs;
        for (int i = t; i < CIN * HW / 4; i += 256) xsv[i] = xv[i];
    }
    __syncthreads();

    const int cp  = cg * 64 + (t >> 2);
    const int hw0 = (t & 3) * 4;

    float bv = b1[cp];
    float a0 = bv, a1 = bv, a2 = bv, a3 = bv;

    const float4* w1v = (const float4*)(W1 + (size_t)cp * CIN);
    #pragma unroll 4
    for (int c4 = 0; c4 < CIN / 4; c4++) {
        float4 w = w1v[c4];
        const float* xp = xs + c4 * 4 * HW + hw0;
        a0 += w.x * xp[0];      a1 += w.x * xp[1];      a2 += w.x * xp[2];      a3 += w.x * xp[3];
        a0 += w.y * xp[16];     a1 += w.y * xp[17];     a2 += w.y * xp[18];     a3 += w.y * xp[19];
        a0 += w.z * xp[32];     a1 += w.z * xp[33];     a2 += w.z * xp[34];     a3 += w.z * xp[35];
        a0 += w.w * xp[48];     a1 += w.w * xp[49];     a2 += w.w * xp[50];     a3 += w.w * xp[51];
    }

    float4 r;
    r.x = fmaxf(a0, 0.f); r.y = fmaxf(a1, 0.f); r.z = fmaxf(a2, 0.f); r.w = fmaxf(a3, 0.f);
    *(float4*)(g_y + ((size_t)b * CIN + cp) * HW + hw0) = r;

    if (cg == 0) {
        float s = 0.f;
        #pragma unroll
        for (int h = 0; h < HW; h++) s += xs[t * HW + h];
        g_xsum[b * CIN + t] = s;
    }
}

// ============================================================
// K2: G[b][k] = sum_hw x[b,c,hw]*y[b,c',hw], k = c*256+c'
// writes chunk-blocked g_G2[k>>5][b][k&31]
// ============================================================
__global__ void __launch_bounds__(256) k2_G(const float* __restrict__ x)
{
    __shared__ float xs2[32 * HW];
    const int b  = blockIdx.y;
    const int cg = blockIdx.x;
    const int t  = threadIdx.x;

    {
        const float4* xv = (const float4*)(x + ((size_t)b * CIN + cg * 32) * HW);
        float4*       sv = (float4*)xs2;
        for (int i = t; i < 32 * HW / 4; i += 256) sv[i] = xv[i];
    }

    float yr[HW];
    {
        const float4* yv = (const float4*)(g_y + ((size_t)b * CIN + t) * HW);
        #pragma unroll
        for (int i = 0; i < 4; i++) {
            float4 v = yv[i];
            yr[i * 4 + 0] = v.x; yr[i * 4 + 1] = v.y; yr[i * 4 + 2] = v.z; yr[i * 4 + 3] = v.w;
        }
    }
    __syncthreads();

    const int wk  = t >> 5;
    const int kin = t & 31;

    #pragma unroll 4
    for (int j = 0; j < 32; j++) {
        const float* xj = xs2 + j * HW;
        float v = 0.f;
        #pragma unroll
        for (int h = 0; h < HW; h++) v += xj[h] * yr[h];
        int kc = (cg * 32 + j) * 8 + wk;
        g_G2[(size_t)kc * (NB * KCH) + b * KCH + kin] = v;
    }
}

// ============================================================
// K_bias: bias[b][o] = sum_c b2[o*256+c]*Xsum[b][c] -> g_part slot S3
// ============================================================
__global__ void __launch_bounds__(256) k_bias(const float* __restrict__ b2)
{
    __shared__ float xsT[CIN][33];
    __shared__ float b2s[8][CIN];
    const int tid = threadIdx.x;
    const int o0  = blockIdx.x * 8;

    for (int i = tid; i < NB * CIN; i += 256) {
        int b = i >> 8, c = i & 255;
        xsT[c][b] = g_xsum[i];
    }
    for (int i = tid; i < 8 * CIN; i += 256) {
        b2s[i >> 8][i & 255] = b2[(size_t)o0 * CIN + i];
    }
    __syncthreads();

    const int b  = tid & 31;
    const int ol = tid >> 5;
    float acc = 0.f;
    #pragma unroll 8
    for (int c = 0; c < CIN; c++) acc += b2s[ol][c] * xsT[c][b];

    g_part[((size_t)S3 * NB + b) * COUT + o0 + ol] = acc;
}

// ============================================================
// K3: part[s][b][o] = sum_{k in slice} G[b][k] * W2[o*KTOT + k]
// grid (COUT/OTB=2, S3=128), 256 threads
// thread tile: 4 b x 8 o, k-pair packed accumulators (f32x2)
// thread map: bg = t&7 (b = 4bg..4bg+3), og = t>>3 (o = o0B+8og..+7)
// smem: double-buffered, XOR-swizzled (16B granules), filled via cp.async
//   sW[o][kq]: addr = o*128 + ((kq ^ (o&7) ^ ((o>>3)&7))&7)*16      (32 KB/buf)
//   sG[b][kq]: addr = b*128 + ((kq ^ (b>>2))&7)*16                  ( 4 KB/buf)
// ============================================================
#define SW_BUF 32768
#define SG_BUF 4096
#define SMEM_K3 (2 * (SW_BUF + SG_BUF))   // 73728 bytes

__global__ void __launch_bounds__(256, 2) k3_gemm(const float* __restrict__ W2)
{
    extern __shared__ char dsm[];
    const unsigned sWb = (unsigned)__cvta_generic_to_shared(dsm);
    const unsigned sGb = sWb + 2 * SW_BUF;

    const int og   = blockIdx.x;
    const int s    = blockIdx.y;
    const int tid  = threadIdx.x;
    const int bg   = tid & 7;           // b group: b = 4bg..4bg+3
    const int ogr  = tid >> 3;          // o group: o = o0B + 8*ogr .. +7
    const int ogx  = ogr & 7;
    const int o0B  = og * OTB;
    const int kbase = s * (NCH * KCH);
    const int kc0   = kbase >> 5;       // g_G2 chunk base

    // staging mapping: kq = tid&7, ro = tid>>3
    const int skq = tid & 7;
    const int sro = tid >> 3;

    ull acc[4][8];
    #pragma unroll
    for (int i = 0; i < 4; i++)
        #pragma unroll
        for (int j = 0; j < 8; j++) acc[i][j] = 0ull;

    // ---- stage one chunk into buffer buf ----
    auto stage = [&](int ch, int buf) {
        const int k0 = kbase + ch * KCH;
        const unsigned wdst0 = sWb + buf * SW_BUF;
        #pragma unroll
        for (int r = 0; r < 8; r++) {
            int o = r * 32 + sro;
            const float* src = W2 + (size_t)(o0B + o) * KTOT + k0 + skq * 4;
            unsigned dst = wdst0 + o * 128 + (((skq ^ (o & 7) ^ ((o >> 3) & 7)) & 7) << 4);
            CP_ASYNC16(dst, src);
        }
        {
            int b = sro;  // 0..31
            const float* src = g_G2 + (size_t)(kc0 + ch) * (NB * KCH) + b * KCH + skq * 4;
            unsigned dst = sGb + buf * SG_BUF + b * 128 + (((skq ^ (b >> 2)) & 7) << 4);
            CP_ASYNC16(dst, src);
        }
    };

    stage(0, 0);
    CP_COMMIT();

    for (int ch = 0; ch < NCH; ch++) {
        const int buf = ch & 1;
        if (ch + 1 < NCH) {
            stage(ch + 1, (ch + 1) & 1);
            CP_COMMIT();
            CP_WAIT(1);
        } else {
            CP_WAIT(0);
        }
        __syncthreads();

        const unsigned wbase = sWb + buf * SW_BUF;
        const unsigned gbase = sGb + buf * SG_BUF;

        #pragma unroll
        for (int kq = 0; kq < 8; kq++) {
            // G for this thread's 4 b at this k-quad (2 k-pairs per b)
            ull g0[4], g1[4];
            #pragma unroll
            for (int bi = 0; bi < 4; bi++) {
                unsigned ga = gbase + (4 * bg + bi) * 128 + (((kq ^ bg) & 7) << 4);
                LDS2(g0[bi], g1[bi], ga);
            }
            #pragma unroll
            for (int oo = 0; oo < 8; oo++) {
                ull w0, w1;
                unsigned wa = wbase + (ogr * 8 + oo) * 128 + (((kq ^ oo ^ ogx) & 7) << 4);
                LDS2(w0, w1, wa);
                #pragma unroll
                for (int bi = 0; bi < 4; bi++) {
                    FMA2(acc[bi][oo], g0[bi], w0);
                    FMA2(acc[bi][oo], g1[bi], w1);
                }
            }
        }
        __syncthreads();
    }

    // epilogue: 4 b x 8 o -> two float4 stores per b
    #pragma unroll
    for (int bi = 0; bi < 4; bi++) {
        const int b = 4 * bg + bi;
        float r[8];
        #pragma unroll
        for (int oo = 0; oo < 8; oo++) r[oo] = unpack_sum(acc[bi][oo]);
        float* dst = g_part + ((size_t)s * NB + b) * COUT + o0B + ogr * 8;
        *(float4*)(dst + 0) = make_float4(r[0], r[1], r[2], r[3]);
        *(float4*)(dst + 4) = make_float4(r[4], r[5], r[6], r[7]);
    }
}

// ============================================================
// K4: out[b][o] = sum over S3+1 partial slots
// ============================================================
__global__ void __launch_bounds__(256) k4_reduce(float* __restrict__ out)
{
    __shared__ float red[256];
    const int tid = threadIdx.x;
    const int r   = tid >> 6;
    const int ml  = tid & 63;
    const int m   = blockIdx.x * 64 + ml;

    const int s0 = r * 32;
    const int s1 = (r == 3) ? (S3 + 1) : (s0 + 32);

    float s = 0.f;
    #pragma unroll 8
    for (int sp = s0; sp < s1; sp++)
        s += g_part[(size_t)sp * (NB * COUT) + m];

    red[tid] = s;
    __syncthreads();
    if (tid < 64) {
        out[blockIdx.x * 64 + tid] =
            red[tid] + red[tid + 64] + red[tid + 128] + red[tid + 192];
    }
}

// ============================================================
extern "C" void kernel_launch(void* const* d_in, const int* in_sizes, int n_in,
                              void* d_out, int out_size)
{
    const float* x  = (const float*)d_in[0];
    const float* W1 = (const float*)d_in[1];
    const float* b1 = (const float*)d_in[2];
    const float* W2 = (const float*)d_in[3];
    const float* b2 = (const float*)d_in[4];
    // d_in[5] (Wa), d_in[6] (ba): attention branch is dead code in the reference.
    float* out = (float*)d_out;

    cudaFuncSetAttribute(k3_gemm, cudaFuncAttributeMaxDynamicSharedMemorySize, SMEM_K3);

    k1_y   <<<dim3(4, NB), 256>>>(x, W1, b1);
    k2_G   <<<dim3(8, NB), 256>>>(x);
    k_bias <<<64, 256>>>(b2);
    k3_gemm<<<dim3(COUT / OTB, S3), 256, SMEM_K3>>>(W2);
    k4_reduce<<<(NB * COUT) / 64, 256>>>(out);
}

// round 7
// speedup vs baseline: 10.1905x; 1.7326x over previous
#include <cuda_runtime.h>
#include <cstdint>

// ---------------- problem constants ----------------
#define NB   32        // batch
#define CIN  256
#define COUT 512
#define HW   16
#define KTOT 65536     // CIN*CIN
#define S3   128       // K-splits in main GEMM
#define KCH  32        // K per chunk
#define NCH  16        // chunks per split
#define OTB  256       // o rows per block
#define RS   36        // smem row stride in floats (144B; conflict-free)

// compensate tf32 truncation of W2 inside HMMA (mean relative shrink ~3.25e-4)
#define W2_TRUNC_COMP 1.000325f

#define CP_ASYNC16(dst, src) \
    asm volatile("cp.async.cg.shared.global [%0], [%1], 16;" :: "r"(dst), "l"(src))
#define CP_COMMIT() asm volatile("cp.async.commit_group;")
#define CP_WAIT(n)  asm volatile("cp.async.wait_group %0;" :: "n"(n))

// m16n8k8 tf32 HMMA (sm_80+ baseline feature; works on sm_103 non-'a' target)
#define MMA8(d0,d1,d2,d3, a0,a1,a2,a3, b0,b1) \
    asm volatile("mma.sync.aligned.m16n8k8.row.col.f32.tf32.tf32.f32 " \
        "{%0,%1,%2,%3}, {%4,%5,%6,%7}, {%8,%9}, {%0,%1,%2,%3};" \
        : "+f"(d0), "+f"(d1), "+f"(d2), "+f"(d3) \
        : "r"(a0), "r"(a1), "r"(a2), "r"(a3), "r"(b0), "r"(b1))

// ---------------- scratch ----------------
__device__ float g_y[NB * CIN * HW];              // 512 KB
__device__ float g_xsum[NB * CIN];                //  32 KB
__device__ float g_G2[(KTOT / KCH) * NB * KCH];   // [kchunk][b][kin]  8 MB (tf32-rounded, scaled)
__device__ float g_part[S3 * NB * COUT];          // [s][b][o]       8.4 MB

// ============================================================
// K1: y = relu(W1 x + b1), Xsum = sum_hw x
// ============================================================
__global__ void __launch_bounds__(256) k1_y(const float* __restrict__ x,
                                            const float* __restrict__ W1,
                                            const float* __restrict__ b1)
{
    __shared__ float xs[CIN * HW];
    const int b  = blockIdx.y;
    const int cg = blockIdx.x;
    const int t  = threadIdx.x;

    {
        const float4* xv  = (const float4*)(x + (size_t)b * CIN * HW);
        float4*       xsv = (float4*)xs;
        for (int i = t; i < CIN * HW / 4; i += 256) xsv[i] = xv[i];
    }
    __syncthreads();

    const int cp  = cg * 64 + (t >> 2);
    const int hw0 = (t & 3) * 4;

    float bv = b1[cp];
    float a0 = bv, a1 = bv, a2 = bv, a3 = bv;

    const float4* w1v = (const float4*)(W1 + (size_t)cp * CIN);
    #pragma unroll 4
    for (int c4 = 0; c4 < CIN / 4; c4++) {
        float4 w = w1v[c4];
        const float* xp = xs + c4 * 4 * HW + hw0;
        a0 += w.x * xp[0];      a1 += w.x * xp[1];      a2 += w.x * xp[2];      a3 += w.x * xp[3];
        a0 += w.y * xp[16];     a1 += w.y * xp[17];     a2 += w.y * xp[18];     a3 += w.y * xp[19];
        a0 += w.z * xp[32];     a1 += w.z * xp[33];     a2 += w.z * xp[34];     a3 += w.z * xp[35];
        a0 += w.w * xp[48];     a1 += w.w * xp[49];     a2 += w.w * xp[50];     a3 += w.w * xp[51];
    }

    float4 r;
    r.x = fmaxf(a0, 0.f); r.y = fmaxf(a1, 0.f); r.z = fmaxf(a2, 0.f); r.w = fmaxf(a3, 0.f);
    *(float4*)(g_y + ((size_t)b * CIN + cp) * HW + hw0) = r;

    if (cg == 0) {
        float s = 0.f;
        #pragma unroll
        for (int h = 0; h < HW; h++) s += xs[t * HW + h];
        g_xsum[b * CIN + t] = s;
    }
}

// ============================================================
// K2: G[b][k] = sum_hw x[b,c,hw]*y[b,c',hw], k = c*256+c'
// scale by W2_TRUNC_COMP, round to tf32-nearest,
// write chunk-blocked g_G2[k>>5][b][k&31]
// ============================================================
__global__ void __launch_bounds__(256) k2_G(const float* __restrict__ x)
{
    __shared__ float xs2[32 * HW];
    const int b  = blockIdx.y;
    const int cg = blockIdx.x;
    const int t  = threadIdx.x;

    {
        const float4* xv = (const float4*)(x + ((size_t)b * CIN + cg * 32) * HW);
        float4*       sv = (float4*)xs2;
        for (int i = t; i < 32 * HW / 4; i += 256) sv[i] = xv[i];
    }

    float yr[HW];
    {
        const float4* yv = (const float4*)(g_y + ((size_t)b * CIN + t) * HW);
        #pragma unroll
        for (int i = 0; i < 4; i++) {
            float4 v = yv[i];
            yr[i * 4 + 0] = v.x; yr[i * 4 + 1] = v.y; yr[i * 4 + 2] = v.z; yr[i * 4 + 3] = v.w;
        }
    }
    __syncthreads();

    const int wk  = t >> 5;
    const int kin = t & 31;

    #pragma unroll 4
    for (int j = 0; j < 32; j++) {
        const float* xj = xs2 + j * HW;
        float v = 0.f;
        #pragma unroll
        for (int h = 0; h < HW; h++) v += xj[h] * yr[h];
        v *= W2_TRUNC_COMP;
        float vt;
        asm("cvt.rna.tf32.f32 %0, %1;" : "=f"(vt) : "f"(v));
        int kc = (cg * 32 + j) * 8 + wk;
        g_G2[(size_t)kc * (NB * KCH) + b * KCH + kin] = vt;
    }
}

// ============================================================
// K3: tf32 HMMA GEMM: part[s][b][o] = sum_{k in slice} G[b][k]*W2[o*KTOT+k]
// grid (COUT/OTB=2, S3=128), 256 threads (8 warps)
// warp w: o rows [w*32, w*32+32), all 32 b; 2 m-tiles x 4 n-tiles of m16n8k8
// smem: double-buffered A(256 x 32k) + B(32 x 32k), rows stride RS=36 floats
// ============================================================
#define SA_FBUF (OTB * RS)          // 9216 floats per A buffer
#define SB_FBUF (NB * RS)           // 1152 floats per B buffer
#define SMEM_K3 ((2 * SA_FBUF + 2 * SB_FBUF) * 4)   // 82944 bytes

__global__ void __launch_bounds__(256, 2) k3_gemm(const float* __restrict__ W2)
{
    extern __shared__ float dsm[];
    float* sA = dsm;                  // [2][OTB][RS]
    float* sB = dsm + 2 * SA_FBUF;    // [2][NB][RS]

    const int og   = blockIdx.x;
    const int s    = blockIdx.y;
    const int tid  = threadIdx.x;
    const int lane = tid & 31;
    const int w    = tid >> 5;
    const int g    = lane >> 2;       // fragment group row
    const int t4   = lane & 3;        // thread-in-group (k index)
    const int o0B  = og * OTB;
    const int warpO = w * 32;
    const int kbase = s * (NCH * KCH);
    const int kc0   = kbase >> 5;

    const int sro = tid >> 3;   // staging row 0..31
    const int skq = tid & 7;    // 16B granule

    const unsigned sAaddr = (unsigned)__cvta_generic_to_shared(sA);
    const unsigned sBaddr = (unsigned)__cvta_generic_to_shared(sB);

    float d[2][4][4];
    #pragma unroll
    for (int mi = 0; mi < 2; mi++)
        #pragma unroll
        for (int ni = 0; ni < 4; ni++)
            #pragma unroll
            for (int r = 0; r < 4; r++) d[mi][ni][r] = 0.f;

    auto stage = [&](int ch, int buf) {
        const int k0 = kbase + ch * KCH;
        #pragma unroll
        for (int i = 0; i < 8; i++) {
            int row = sro + i * 32;
            const float* src = W2 + (size_t)(o0B + row) * KTOT + k0 + skq * 4;
            unsigned dst = sAaddr + (buf * SA_FBUF + row * RS + skq * 4) * 4;
            CP_ASYNC16(dst, src);
        }
        {
            const float* src = g_G2 + (size_t)(kc0 + ch) * (NB * KCH) + sro * KCH + skq * 4;
            unsigned dst = sBaddr + (buf * SB_FBUF + sro * RS + skq * 4) * 4;
            CP_ASYNC16(dst, src);
        }
    };

    stage(0, 0);
    CP_COMMIT();

    for (int ch = 0; ch < NCH; ch++) {
        const int buf = ch & 1;
        if (ch + 1 < NCH) {
            stage(ch + 1, buf ^ 1);
            CP_COMMIT();
            CP_WAIT(1);
        } else {
            CP_WAIT(0);
        }
        __syncthreads();

        const float* A = sA + buf * SA_FBUF;
        const float* B = sB + buf * SB_FBUF;

        #pragma unroll
        for (int k8 = 0; k8 < 4; k8++) {
            const int kq0 = k8 * 8;

            unsigned bf[4][2];
            #pragma unroll
            for (int ni = 0; ni < 4; ni++) {
                const float* bp = B + (ni * 8 + g) * RS + kq0 + t4;
                bf[ni][0] = __float_as_uint(bp[0]);
                bf[ni][1] = __float_as_uint(bp[4]);
            }
            unsigned af[2][4];
            #pragma unroll
            for (int mi = 0; mi < 2; mi++) {
                const float* ap = A + (warpO + mi * 16 + g) * RS + kq0 + t4;
                af[mi][0] = __float_as_uint(ap[0]);
                af[mi][1] = __float_as_uint(ap[8 * RS]);
                af[mi][2] = __float_as_uint(ap[4]);
                af[mi][3] = __float_as_uint(ap[8 * RS + 4]);
            }
            #pragma unroll
            for (int mi = 0; mi < 2; mi++)
                #pragma unroll
                for (int ni = 0; ni < 4; ni++)
                    MMA8(d[mi][ni][0], d[mi][ni][1], d[mi][ni][2], d[mi][ni][3],
                         af[mi][0], af[mi][1], af[mi][2], af[mi][3],
                         bf[ni][0], bf[ni][1]);
        }
        __syncthreads();
    }

    // epilogue: D rows = o, cols = b
    #pragma unroll
    for (int mi = 0; mi < 2; mi++) {
        const int o = o0B + warpO + mi * 16 + g;
        #pragma unroll
        for (int ni = 0; ni < 4; ni++) {
            const int b = ni * 8 + 2 * t4;
            float* p0 = g_part + ((size_t)s * NB + b) * COUT + o;
            float* p1 = p0 + COUT;   // b+1
            p0[0] = d[mi][ni][0];
            p1[0] = d[mi][ni][1];
            p0[8] = d[mi][ni][2];
            p1[8] = d[mi][ni][3];
        }
    }
}

// ============================================================
// K4: out[b][o] = sum_s part[s][b][o] + sum_c b2[o*256+c]*Xsum[b][c]
// grid 256 blocks (64 outputs each, same b), 256 threads
// (ml = tid>>2 -> output, r = tid&3 -> quarter reducer), shfl-reduce
// ============================================================
__global__ void __launch_bounds__(256) k4_reduce(const float* __restrict__ b2,
                                                 float* __restrict__ out)
{
    __shared__ float xs[CIN];
    const int tid = threadIdx.x;
    const int b   = blockIdx.x >> 3;
    const int o0  = (blockIdx.x & 7) * 64;

    if (tid < CIN / 4)
        ((float4*)xs)[tid] = ((const float4*)(g_xsum + b * CIN))[tid];
    __syncthreads();

    const int ml = tid >> 2;
    const int r  = tid & 3;
    const int o  = o0 + ml;
    const int m  = (b << 9) + o;

    float v = 0.f;

    #pragma unroll 8
    for (int sp = r * (S3 / 4); sp < (r + 1) * (S3 / 4); sp++)
        v += g_part[(size_t)sp * (NB * COUT) + m];

    const float4* b2r = (const float4*)(b2 + (size_t)o * CIN);
    #pragma unroll
    for (int i = 0; i < 16; i++) {
        float4 wv = b2r[r + i * 4];
        const float* xc = xs + (r + i * 4) * 4;
        v += wv.x * xc[0] + wv.y * xc[1] + wv.z * xc[2] + wv.w * xc[3];
    }

    v += __shfl_xor_sync(0xFFFFFFFF, v, 1);
    v += __shfl_xor_sync(0xFFFFFFFF, v, 2);
    if (r == 0) out[m] = v;
}

// ============================================================
extern "C" void kernel_launch(void* const* d_in, const int* in_sizes, int n_in,
                              void* d_out, int out_size)
{
    const float* x  = (const float*)d_in[0];
    const float* W1 = (const float*)d_in[1];
    const float* b1 = (const float*)d_in[2];
    const float* W2 = (const float*)d_in[3];
    const float* b2 = (const float*)d_in[4];
    // d_in[5] (Wa), d_in[6] (ba): attention branch is dead code in the reference.
    float* out = (float*)d_out;

    cudaFuncSetAttribute(k3_gemm, cudaFuncAttributeMaxDynamicSharedMemorySize, SMEM_K3);

    k1_y   <<<dim3(4, NB), 256>>>(x, W1, b1);
    k2_G   <<<dim3(8, NB), 256>>>(x);
    k3_gemm<<<dim3(COUT / OTB, S3), 256, SMEM_K3>>>(W2);
    k4_reduce<<<(NB * COUT) / 64, 256>>>(b2, out);
}